// round 12
// baseline (speedup 1.0000x reference)
#include <cuda_runtime.h>
#include <math_constants.h>

#define B_   16
#define N_   16384
#define M_   256
#define TPB  256
#define PPB  256                       // points per block
#define HALF 128                       // threads per m-half
#define NBLK ((N_ / PPB) * B_)         // 1024 blocks

// -------- scratch (device globals; zero at load; last block re-zeroes) --------
__device__ float    g_cnt[B_ * M_];
__device__ float    g_sum[3 * B_ * M_];   // plane-major: [k][b][m]
__device__ float    g_sq [B_ * M_];
__device__ float    g_sl1;
__device__ unsigned g_done;

// ===== fused kernel: argmin cdist (8-aligned m-split halves, inf-padded) +
//       balanced per-point epilogue + smem segment stats + last-block finalize =====
__global__ __launch_bounds__(TPB) void k_main(
    const float* __restrict__ data, const float* __restrict__ cp,
    const float* __restrict__ off,  const int* __restrict__ tc,
    const int* __restrict__ lab,    float* __restrict__ out)
{
    __shared__ float4 sc[M_];                          // {cx,cy,cz, cn | +inf}
    __shared__ float s_cnt[M_], s_sx[M_], s_sy[M_], s_sz[M_], s_sq[M_];
    __shared__ float s_bd2[2][PPB];                    // per-half best dist
    __shared__ int   s_bi2[2][PPB];
    __shared__ float s_red[TPB / 32];
    __shared__ unsigned s_last;

    const int b = blockIdx.y;
    const int t = threadIdx.x;
    const int T = tc[b];

    const int pid  = t & (HALF - 1);
    const int half = t >> 7;                            // 0 or 1
    const int base = blockIdx.x * PPB;
    const int n0 = base + pid;                          // this thread's 2 points
    const int n1 = n0 + HALF;
    const float* dB = data + (size_t)b * 3 * N_;
    const float* oB = off  + (size_t)b * 3 * N_;

    // hoisted point loads: latency hides under the contact fill + barrier
    float px0 = dB[n0], py0 = dB[N_ + n0], pz0 = dB[2 * N_ + n0];
    float px1 = dB[n1], py1 = dB[N_ + n1], pz1 = dB[2 * N_ + n1];

    {   // TPB == M_: one contact per thread; m >= T gets cn=+inf (d=+inf)
        float cx = cp[(b * M_ + t) * 3 + 0];
        float cy = cp[(b * M_ + t) * 3 + 1];
        float cz = cp[(b * M_ + t) * 3 + 2];
        float cn = (t < T) ? (cx * cx + cy * cy) + cz * cz   // ref op order
                           : CUDART_INF_F;
        sc[t] = make_float4(cx, cy, cz, cn);
        s_cnt[t] = 0.f; s_sx[t] = 0.f; s_sy[t] = 0.f; s_sz[t] = 0.f; s_sq[t] = 0.f;
    }

    float pn0 = (px0 * px0 + py0 * py0) + pz0 * pz0;    // ref op order
    float pn1 = (px1 * px1 + py1 * py1) + pz1 * pz1;
    __syncthreads();

    // 8-aligned half ranges; straddle chunk scanned by BOTH halves (identical
    // values; strict '<' ascending combine keeps exact first index).
    const int mh   = T >> 1;
    const int mbeg = half ? (mh & ~7)       : 0;
    const int mend = half ? ((T + 7) & ~7)  : ((mh + 7) & ~7);

    // argmin; replicate reference fp exactly:
    // d = (||p||^2 + ||c||^2) - 2*dot == fmaf(-2, dot, pn + cn)  (2*dot exact)
    int   bi0 = 0, bi1 = 0;
    float bd0 = CUDART_INF_F;
    float bd1 = bd0;
    for (int m = mbeg; m < mend; m += 8) {
        #pragma unroll
        for (int j = 0; j < 8; j++) {
            float4 c = sc[m + j];                       // LDS.128 broadcast
            float dot0 = fmaf(pz0, c.z, fmaf(py0, c.y, px0 * c.x));
            float d0   = fmaf(-2.0f, dot0, pn0 + c.w);
            if (d0 < bd0) { bd0 = d0; bi0 = m + j; }
            float dot1 = fmaf(pz1, c.z, fmaf(py1, c.y, px1 * c.x));
            float d1   = fmaf(-2.0f, dot1, pn1 + c.w);
            if (d1 < bd1) { bd1 = d1; bi1 = m + j; }
        }
    }

    s_bd2[half][pid]        = bd0; s_bi2[half][pid]        = bi0;
    s_bd2[half][HALF + pid] = bd1; s_bi2[half][HALF + pid] = bi1;
    __syncthreads();

    // ---- balanced per-point epilogue: each of 256 threads owns one point ----
    // thread t's point (base+t) is one of the two it already loaded:
    //   half==0 -> (px0,py0,pz0),  half==1 -> (px1,py1,pz1)
    const bool has = (T > 0);
    float ls = 0.f;
    {
        float bd = s_bd2[0][t];
        int   bi = s_bi2[0][t];
        float v  = s_bd2[1][t];
        if (v < bd) { bd = v; bi = s_bi2[1][t]; }       // strict '<': first index

        const int n = base + t;
        float px = half ? px1 : px0;
        float py = half ? py1 : py0;
        float pz = half ? pz1 : pz0;
        float gx = 0.f, gy = 0.f, gz = 0.f;
        if (has) {
            float4 c = sc[bi];
            gx = c.x - px; gy = c.y - py; gz = c.z - pz;
        }
        float* outB = out + (size_t)b * 3 * N_;
        outB[n] = gx; outB[N_ + n] = gy; outB[2 * N_ + n] = gz;

        float ox = oB[n], oy = oB[N_ + n], oz = oB[2 * N_ + n];
        if (lab[b] == 1) {
            float d, a;
            d = gx - ox; a = fabsf(d); ls += (a < 1.f) ? 0.5f * d * d : a - 0.5f;
            d = gy - oy; a = fabsf(d); ls += (a < 1.f) ? 0.5f * d * d : a - 0.5f;
            d = gz - oz; a = fabsf(d); ls += (a < 1.f) ? 0.5f * d * d : a - 0.5f;
        }
        if (has) {
            float ex = px + ox, ey = py + oy, ez = pz + oz;
            atomicAdd(&s_cnt[bi], 1.f);
            atomicAdd(&s_sx[bi], ex); atomicAdd(&s_sy[bi], ey); atomicAdd(&s_sz[bi], ez);
            atomicAdd(&s_sq[bi], (ex * ex + ey * ey) + ez * ez);
        }
    }

    // smooth-L1 block reduce -> one global atomic per block
    #pragma unroll
    for (int o = 16; o > 0; o >>= 1) ls += __shfl_down_sync(0xffffffffu, ls, o);
    if ((t & 31) == 0) s_red[t >> 5] = ls;
    __syncthreads();
    if (t == 0) {
        float s = 0.f;
        #pragma unroll
        for (int w = 0; w < TPB / 32; w++) s += s_red[w];
        if (s != 0.f) atomicAdd(&g_sl1, s);
    }

    // flush segment stats (one contact per thread)
    if (has) {
        float c = s_cnt[t];
        if (c != 0.f) {
            int idx = b * M_ + t;
            atomicAdd(&g_cnt[idx], c);
            atomicAdd(&g_sum[0 * B_ * M_ + idx], s_sx[t]);
            atomicAdd(&g_sum[1 * B_ * M_ + idx], s_sy[t]);
            atomicAdd(&g_sum[2 * B_ * M_ + idx], s_sz[t]);
            atomicAdd(&g_sq[idx], s_sq[t]);
        }
    }

    // ---- last-block finalize ----
    __threadfence();
    if (t == 0) s_last = (atomicAdd(&g_done, 1u) == (unsigned)(NBLK - 1));
    __syncthreads();
    if (!s_last) return;

    __shared__ int s_tc[B_];
    if (t < B_) s_tc[t] = tc[t];
    __syncthreads();

    float acc = 0.f;
    #pragma unroll
    for (int idx = t; idx < B_ * M_; idx += TPB) {
        int bb = idx >> 8;                              // M_ == 256
        float c  = __ldcg(&g_cnt[idx]);
        float sx = __ldcg(&g_sum[0 * B_ * M_ + idx]);
        float sy = __ldcg(&g_sum[1 * B_ * M_ + idx]);
        float sz = __ldcg(&g_sum[2 * B_ * M_ + idx]);
        float sq = __ldcg(&g_sq[idx]);
        if (s_tc[bb] > 0 && c > 0.f) {
            float vs = sq - ((sx * sx + sy * sy) + sz * sz) / c;
            acc += vs / c;
        }
        g_cnt[idx] = 0.f; g_sq[idx] = 0.f;              // re-zero for next replay
        g_sum[0 * B_ * M_ + idx] = 0.f;
        g_sum[1 * B_ * M_ + idx] = 0.f;
        g_sum[2 * B_ * M_ + idx] = 0.f;
    }
    #pragma unroll
    for (int o = 16; o > 0; o >>= 1) acc += __shfl_down_sync(0xffffffffu, acc, o);
    if ((t & 31) == 0) s_red[t >> 5] = acc;

    float nvalid = 0.f, nsel = 0.f;
    if (t < 32) {
        int v = (t < B_) ? s_tc[t] : 0;
        int l = (t < B_) ? lab[t] : 0;
        unsigned mv = __ballot_sync(0xffffffffu, v > 0);
        unsigned ml = __ballot_sync(0xffffffffu, l == 1);
        nvalid = (float)__popc(mv);
        nsel   = (float)__popc(ml);
    }
    __syncthreads();

    if (t == 0) {
        float vs = 0.f;
        #pragma unroll
        for (int w = 0; w < TPB / 32; w++) vs += s_red[w];
        nsel *= 3.0f * (float)N_;
        float sl1 = __ldcg(&g_sl1);
        float offset_loss = (nsel > 0.f) ? sl1 / fmaxf(nsel, 1.0f) : 0.f;
        float var_loss    = vs / (nvalid + 1e-16f);
        out[(size_t)B_ * 3 * N_] = offset_loss * 10.0f + var_loss * 2.0f;
        g_sl1 = 0.f;
        g_done = 0u;
    }
}

extern "C" void kernel_launch(void* const* d_in, const int* in_sizes, int n_in,
                              void* d_out, int out_size) {
    const float* data = (const float*)d_in[0];
    const float* cp   = (const float*)d_in[1];
    const float* off  = (const float*)d_in[2];
    const int*   tc   = (const int*)d_in[3];
    const int*   lab  = (const int*)d_in[4];
    float* out = (float*)d_out;

    dim3 grid(N_ / PPB, B_);
    k_main<<<grid, TPB>>>(data, cp, off, tc, lab, out);
}

// round 13
// speedup vs baseline: 1.0523x; 1.0523x over previous
#include <cuda_runtime.h>

#define B_   16
#define N_   16384
#define M_   256
#define TPB  256
#define PPB  256                       // points per block
#define HALF 128                       // threads per m-half
#define NBLK ((N_ / PPB) * B_)         // 1024 blocks

// -------- scratch (device globals; zero at load; last block re-zeroes) --------
__device__ float    g_cnt[B_ * M_];
__device__ float    g_sum[3 * B_ * M_];   // plane-major: [k][b][m]
__device__ float    g_sq [B_ * M_];
__device__ float    g_sl1;
__device__ unsigned g_done;

// ===== fused kernel: argmin cdist (m-split halves) + balanced per-point
//       epilogue + smem segment stats + last-block finalize =====
__global__ __launch_bounds__(TPB) void k_main(
    const float* __restrict__ data, const float* __restrict__ cp,
    const float* __restrict__ off,  const int* __restrict__ tc,
    const int* __restrict__ lab,    float* __restrict__ out)
{
    __shared__ float4 sc[M_];                          // {cx,cy,cz,||c||^2}
    __shared__ float s_cnt[M_], s_sx[M_], s_sy[M_], s_sz[M_], s_sq[M_];
    __shared__ float s_bd2[2][PPB];                    // per-half best dist
    __shared__ int   s_bi2[2][PPB];
    __shared__ float s_red[TPB / 32];
    __shared__ unsigned s_last;

    const int b = blockIdx.y;
    const int t = threadIdx.x;
    const int T = tc[b];

    const int pid  = t & (HALF - 1);
    const int half = t >> 7;                            // 0 or 1
    const int base = blockIdx.x * PPB;
    const int n0 = base + pid;                          // this thread's 2 points
    const int n1 = n0 + HALF;
    const float* dB = data + (size_t)b * 3 * N_;
    const float* oB = off  + (size_t)b * 3 * N_;

    // hoisted point loads: LDG latency hides under the contact fill + barrier
    float px0 = dB[n0], py0 = dB[N_ + n0], pz0 = dB[2 * N_ + n0];
    float px1 = dB[n1], py1 = dB[N_ + n1], pz1 = dB[2 * N_ + n1];

    {   // TPB == M_: one contact per thread
        float cx = cp[(b * M_ + t) * 3 + 0];
        float cy = cp[(b * M_ + t) * 3 + 1];
        float cz = cp[(b * M_ + t) * 3 + 2];
        sc[t] = make_float4(cx, cy, cz, (cx * cx + cy * cy) + cz * cz);
        s_cnt[t] = 0.f; s_sx[t] = 0.f; s_sy[t] = 0.f; s_sz[t] = 0.f; s_sq[t] = 0.f;
    }

    float pn0 = (px0 * px0 + py0 * py0) + pz0 * pz0;    // ref op order
    float pn1 = (px1 * px1 + py1 * py1) + pz1 * pz1;
    __syncthreads();

    // m-range for this half: [0, T/2) or [T/2, T)
    const int mh = T >> 1;
    const int mbeg = half ? mh : 0;
    const int mend = half ? T  : mh;

    // argmin; replicate reference fp exactly:
    // d = (||p||^2 + ||c||^2) - 2*dot == fmaf(-2, dot, pn + cn)  (2*dot exact)
    int   bi0 = 0, bi1 = 0;
    float bd0 = __int_as_float(0x7f800000);
    float bd1 = bd0;
    #pragma unroll 8
    for (int m = mbeg; m < mend; m++) {
        float4 c = sc[m];                               // LDS.128 broadcast
        float dot0 = fmaf(pz0, c.z, fmaf(py0, c.y, px0 * c.x));
        float d0   = fmaf(-2.0f, dot0, pn0 + c.w);
        if (d0 < bd0) { bd0 = d0; bi0 = m; }
        float dot1 = fmaf(pz1, c.z, fmaf(py1, c.y, px1 * c.x));
        float d1   = fmaf(-2.0f, dot1, pn1 + c.w);
        if (d1 < bd1) { bd1 = d1; bi1 = m; }
    }

    s_bd2[half][pid]        = bd0; s_bi2[half][pid]        = bi0;
    s_bd2[half][HALF + pid] = bd1; s_bi2[half][HALF + pid] = bi1;
    __syncthreads();

    // ---- balanced per-point epilogue: each of 256 threads owns one point ----
    // thread t's point (base+t) is one of the two it already holds in registers:
    //   half==0 -> (px0,py0,pz0),  half==1 -> (px1,py1,pz1)
    const bool has = (T > 0);
    float ls = 0.f;
    {
        float bd = s_bd2[0][t];
        int   bi = s_bi2[0][t];
        float v  = s_bd2[1][t];
        if (v < bd) { bd = v; bi = s_bi2[1][t]; }       // strict '<': first index

        const int n = base + t;
        float px = half ? px1 : px0;
        float py = half ? py1 : py0;
        float pz = half ? pz1 : pz0;
        float gx = 0.f, gy = 0.f, gz = 0.f;
        if (has) {
            float4 c = sc[bi];
            gx = c.x - px; gy = c.y - py; gz = c.z - pz;
        }
        float* outB = out + (size_t)b * 3 * N_;
        outB[n] = gx; outB[N_ + n] = gy; outB[2 * N_ + n] = gz;

        float ox = oB[n], oy = oB[N_ + n], oz = oB[2 * N_ + n];
        if (lab[b] == 1) {
            float d, a;
            d = gx - ox; a = fabsf(d); ls += (a < 1.f) ? 0.5f * d * d : a - 0.5f;
            d = gy - oy; a = fabsf(d); ls += (a < 1.f) ? 0.5f * d * d : a - 0.5f;
            d = gz - oz; a = fabsf(d); ls += (a < 1.f) ? 0.5f * d * d : a - 0.5f;
        }
        if (has) {
            float ex = px + ox, ey = py + oy, ez = pz + oz;
            atomicAdd(&s_cnt[bi], 1.f);
            atomicAdd(&s_sx[bi], ex); atomicAdd(&s_sy[bi], ey); atomicAdd(&s_sz[bi], ez);
            atomicAdd(&s_sq[bi], (ex * ex + ey * ey) + ez * ez);
        }
    }

    // smooth-L1 block reduce -> one global atomic per block
    #pragma unroll
    for (int o = 16; o > 0; o >>= 1) ls += __shfl_down_sync(0xffffffffu, ls, o);
    if ((t & 31) == 0) s_red[t >> 5] = ls;
    __syncthreads();
    if (t == 0) {
        float s = 0.f;
        #pragma unroll
        for (int w = 0; w < TPB / 32; w++) s += s_red[w];
        if (s != 0.f) atomicAdd(&g_sl1, s);
    }

    // flush segment stats (one contact per thread)
    if (has) {
        float c = s_cnt[t];
        if (c != 0.f) {
            int idx = b * M_ + t;
            atomicAdd(&g_cnt[idx], c);
            atomicAdd(&g_sum[0 * B_ * M_ + idx], s_sx[t]);
            atomicAdd(&g_sum[1 * B_ * M_ + idx], s_sy[t]);
            atomicAdd(&g_sum[2 * B_ * M_ + idx], s_sz[t]);
            atomicAdd(&g_sq[idx], s_sq[t]);
        }
    }

    // ---- last-block finalize ----
    __threadfence();
    if (t == 0) s_last = (atomicAdd(&g_done, 1u) == (unsigned)(NBLK - 1));
    __syncthreads();
    if (!s_last) return;

    __shared__ int s_tc[B_];
    if (t < B_) s_tc[t] = tc[t];
    __syncthreads();

    float acc = 0.f;
    #pragma unroll
    for (int idx = t; idx < B_ * M_; idx += TPB) {
        int bb = idx >> 8;                              // M_ == 256
        float c  = __ldcg(&g_cnt[idx]);
        float sx = __ldcg(&g_sum[0 * B_ * M_ + idx]);
        float sy = __ldcg(&g_sum[1 * B_ * M_ + idx]);
        float sz = __ldcg(&g_sum[2 * B_ * M_ + idx]);
        float sq = __ldcg(&g_sq[idx]);
        if (s_tc[bb] > 0 && c > 0.f) {
            float vs = sq - ((sx * sx + sy * sy) + sz * sz) / c;
            acc += vs / c;
        }
        g_cnt[idx] = 0.f; g_sq[idx] = 0.f;              // re-zero for next replay
        g_sum[0 * B_ * M_ + idx] = 0.f;
        g_sum[1 * B_ * M_ + idx] = 0.f;
        g_sum[2 * B_ * M_ + idx] = 0.f;
    }
    #pragma unroll
    for (int o = 16; o > 0; o >>= 1) acc += __shfl_down_sync(0xffffffffu, acc, o);
    if ((t & 31) == 0) s_red[t >> 5] = acc;

    float nvalid = 0.f, nsel = 0.f;
    if (t < 32) {
        int v = (t < B_) ? s_tc[t] : 0;
        int l = (t < B_) ? lab[t] : 0;
        unsigned mv = __ballot_sync(0xffffffffu, v > 0);
        unsigned ml = __ballot_sync(0xffffffffu, l == 1);
        nvalid = (float)__popc(mv);
        nsel   = (float)__popc(ml);
    }
    __syncthreads();

    if (t == 0) {
        float vs = 0.f;
        #pragma unroll
        for (int w = 0; w < TPB / 32; w++) vs += s_red[w];
        nsel *= 3.0f * (float)N_;
        float sl1 = __ldcg(&g_sl1);
        float offset_loss = (nsel > 0.f) ? sl1 / fmaxf(nsel, 1.0f) : 0.f;
        float var_loss    = vs / (nvalid + 1e-16f);
        out[(size_t)B_ * 3 * N_] = offset_loss * 10.0f + var_loss * 2.0f;
        g_sl1 = 0.f;
        g_done = 0u;
    }
}

extern "C" void kernel_launch(void* const* d_in, const int* in_sizes, int n_in,
                              void* d_out, int out_size) {
    const float* data = (const float*)d_in[0];
    const float* cp   = (const float*)d_in[1];
    const float* off  = (const float*)d_in[2];
    const int*   tc   = (const int*)d_in[3];
    const int*   lab  = (const int*)d_in[4];
    float* out = (float*)d_out;

    dim3 grid(N_ / PPB, B_);
    k_main<<<grid, TPB>>>(data, cp, off, tc, lab, out);
}